// round 8
// baseline (speedup 1.0000x reference)
#include <cuda_runtime.h>

// Problem constants: B=4, S=2048, D=1024, U=1024, fp32 throughout.
#define BB 4
#define SSQ 2048
#define DD 1024
#define UU 1024

// Scratch (device globals: allocation-free per harness rules).
// qkv: 96MB combined, weights packed: 12MB, scores: 64MB.
__device__ float g_qkv[(size_t)3 * BB * SSQ * UU];
__device__ float g_w[(size_t)3 * DD * UU];
__device__ float g_s[(size_t)BB * SSQ * SSQ];

typedef unsigned long long u64;

// ---------------------------------------------------------------------------
// Packed fp32x2 helpers (Blackwell FFMA2: double-rate fp32 FMA, rt=1/SMSP).
// ---------------------------------------------------------------------------
__device__ __forceinline__ u64 fma2(u64 a, u64 b, u64 c) {
    u64 d;
    asm("fma.rn.f32x2 %0, %1, %2, %3;" : "=l"(d) : "l"(a), "l"(b), "l"(c));
    return d;
}
__device__ __forceinline__ float2 unpack2(u64 v) {
    float2 f;
    asm("mov.b64 {%0, %1}, %2;" : "=f"(f.x), "=f"(f.y) : "l"(v));
    return f;
}

// ---------------------------------------------------------------------------
// 128x128x16 tiled fp32 GEMM, 256 threads.
// Warp layout: 8 warps as 4(m) x 2(n); lane as 4(m) x 8(n).
// Per-thread microtile: 8x8 split as rows {r0..r0+3, r0+16..r0+19} x
// cols {c0..c0+3, c0+32..c0+35} so every smem read is a contiguous,
// conflict-free LDS.128 (A: 8-lane broadcast -> 1 wavefront; B: 128B -> 1 wf).
// A is stored in smem as pre-duplicated (a,a) f32x2 pairs: no dup movs in
// the inner loop -> 38 instrs per kk for 32 FFMA2 (84% issue ceiling).
//   C = A[M,K] @ B        (TRANS_B=false: B is [K,N] row-major)
//   C = A[M,K] @ B^T      (TRANS_B=true : B is [N,K] row-major)
// Requires M,N % 128 == 0, K % 16 == 0. blockIdx.z batches via strides.
// ---------------------------------------------------------------------------
#define ASTRIDE 260   // floats per k-row of As (260*4B = 16B-aligned, low-conflict)

template <bool TRANS_B>
__global__ __launch_bounds__(256, 2)
void gemm128x128(const float* __restrict__ Ag, const float* __restrict__ Bg,
                 float* __restrict__ Cg, int M, int N, int K,
                 long long sA, long long sB, long long sC)
{
    const float* A = Ag + (long long)blockIdx.z * sA;
    const float* B = Bg + (long long)blockIdx.z * sB;
    float*       C = Cg + (long long)blockIdx.z * sC;

    __shared__ float As[16][ASTRIDE];   // duplicated pairs: [k][2m],[2m+1]
    __shared__ float Bs[16][132];       // [k][n]

    const int tid    = threadIdx.x;
    const int lane   = tid & 31;
    const int wid    = tid >> 5;
    const int warp_m = wid >> 1;              // 0..3  -> 32 rows each
    const int warp_n = wid & 1;               // 0..1  -> 64 cols each
    const int tm     = lane >> 3;             // 0..3
    const int tn     = lane & 7;              // 0..7
    const int r0     = warp_m * 32 + tm * 4;  // rows r0..+3 and r0+16..+19
    const int c0     = warp_n * 64 + tn * 4;  // cols c0..+3 and c0+32..+35
    const int m0     = blockIdx.y * 128;
    const int n0     = blockIdx.x * 128;

    // A staging: 128 rows x 16 k. Each thread: rows (ar, ar+64), 4 k's.
    const int ar  = tid >> 2;           // 0..63
    const int ac4 = (tid & 3) * 4;      // k offset within tile
    const float* Ap = A + (size_t)(m0 + ar) * K + ac4;

    // B staging.
    int br, bc4;
    const float* Bp;
    if (TRANS_B) {                       // B[N,K]
        br  = tid >> 2;  bc4 = (tid & 3) * 4;
        Bp  = B + (size_t)(n0 + br) * K + bc4;
    } else {                             // B[K,N]
        br  = tid >> 5;  bc4 = (tid & 31) * 4;
        Bp  = B + (size_t)br * N + n0 + bc4;
    }

    u64 acc[8][4];
    #pragma unroll
    for (int i = 0; i < 8; ++i)
        #pragma unroll
        for (int j = 0; j < 4; ++j) acc[i][j] = 0ull;

    const int iters = K / 16;

    // Prologue prefetch (tile 0) into registers.
    float4 ra0 = *(const float4*)(Ap);
    float4 ra1 = *(const float4*)(Ap + (size_t)64 * K);
    float4 rb0, rb1;
    if (TRANS_B) {
        rb0 = *(const float4*)(Bp);
        rb1 = *(const float4*)(Bp + (size_t)64 * K);
    } else {
        rb0 = *(const float4*)(Bp);
        rb1 = *(const float4*)(Bp + (size_t)8 * N);
    }

    for (int t = 0; t < iters; ++t) {
        // Commit staged registers to smem. A as duplicated pairs.
        *(float2*)&As[ac4 + 0][2 * ar]        = make_float2(ra0.x, ra0.x);
        *(float2*)&As[ac4 + 1][2 * ar]        = make_float2(ra0.y, ra0.y);
        *(float2*)&As[ac4 + 2][2 * ar]        = make_float2(ra0.z, ra0.z);
        *(float2*)&As[ac4 + 3][2 * ar]        = make_float2(ra0.w, ra0.w);
        *(float2*)&As[ac4 + 0][2 * (ar + 64)] = make_float2(ra1.x, ra1.x);
        *(float2*)&As[ac4 + 1][2 * (ar + 64)] = make_float2(ra1.y, ra1.y);
        *(float2*)&As[ac4 + 2][2 * (ar + 64)] = make_float2(ra1.z, ra1.z);
        *(float2*)&As[ac4 + 3][2 * (ar + 64)] = make_float2(ra1.w, ra1.w);
        if (TRANS_B) {
            Bs[bc4 + 0][br]      = rb0.x; Bs[bc4 + 1][br]      = rb0.y;
            Bs[bc4 + 2][br]      = rb0.z; Bs[bc4 + 3][br]      = rb0.w;
            Bs[bc4 + 0][br + 64] = rb1.x; Bs[bc4 + 1][br + 64] = rb1.y;
            Bs[bc4 + 2][br + 64] = rb1.z; Bs[bc4 + 3][br + 64] = rb1.w;
        } else {
            *(float4*)&Bs[br][bc4]     = rb0;
            *(float4*)&Bs[br + 8][bc4] = rb1;
        }
        __syncthreads();

        // Prefetch next tile (overlaps with compute below).
        if (t + 1 < iters) {
            Ap += 16;
            ra0 = *(const float4*)(Ap);
            ra1 = *(const float4*)(Ap + (size_t)64 * K);
            if (TRANS_B) {
                Bp += 16;
                rb0 = *(const float4*)(Bp);
                rb1 = *(const float4*)(Bp + (size_t)64 * K);
            } else {
                Bp += (size_t)16 * N;
                rb0 = *(const float4*)(Bp);
                rb1 = *(const float4*)(Bp + (size_t)8 * N);
            }
        }

        // Compute: 16 k-steps, 8x8 per thread via packed f32x2 FMA.
        #pragma unroll
        for (int kk = 0; kk < 16; ++kk) {
            // A pairs (already duplicated in smem): 4 x LDS.128, broadcast.
            ulonglong2 aA = *(const ulonglong2*)&As[kk][2 * r0];          // r0, r0+1
            ulonglong2 aB = *(const ulonglong2*)&As[kk][2 * r0 + 4];      // r0+2, r0+3
            ulonglong2 aC = *(const ulonglong2*)&As[kk][2 * (r0 + 16)];   // r0+16, +17
            ulonglong2 aD = *(const ulonglong2*)&As[kk][2 * (r0 + 16) + 4];
            // B pairs: 2 x LDS.128, contiguous 128B per warp.
            ulonglong2 b01 = *(const ulonglong2*)&Bs[kk][c0];        // c0..c0+3
            ulonglong2 b23 = *(const ulonglong2*)&Bs[kk][c0 + 32];   // c0+32..+35

            u64 a[8] = {aA.x, aA.y, aB.x, aB.y, aC.x, aC.y, aD.x, aD.y};
            #pragma unroll
            for (int i = 0; i < 8; ++i) {
                acc[i][0] = fma2(a[i], b01.x, acc[i][0]);
                acc[i][1] = fma2(a[i], b01.y, acc[i][1]);
                acc[i][2] = fma2(a[i], b23.x, acc[i][2]);
                acc[i][3] = fma2(a[i], b23.y, acc[i][3]);
            }
        }
        __syncthreads();
    }

    // Epilogue: rows {r0+i | i<4} and {r0+16+(i-4) | i>=4}; cols c0 and c0+32.
    #pragma unroll
    for (int i = 0; i < 8; ++i) {
        const int row = m0 + r0 + ((i < 4) ? i : (12 + i));
        float2 p0 = unpack2(acc[i][0]);
        float2 p1 = unpack2(acc[i][1]);
        float2 p2 = unpack2(acc[i][2]);
        float2 p3 = unpack2(acc[i][3]);
        size_t off = (size_t)row * N + n0 + c0;
        *(float4*)(C + off)      = make_float4(p0.x, p0.y, p1.x, p1.y);
        *(float4*)(C + off + 32) = make_float4(p2.x, p2.y, p3.x, p3.y);
    }
}

// ---------------------------------------------------------------------------
// Row softmax in place: one 256-thread block per row of length n (=2048).
// ---------------------------------------------------------------------------
__global__ void softmax_rows(float* __restrict__ S, int n)
{
    __shared__ float red[256];
    float* p = S + (size_t)blockIdx.x * n;
    const int tid = threadIdx.x;

    float lmax = -3.402823466e38f;
    for (int i = tid; i < n; i += 256) lmax = fmaxf(lmax, p[i]);
    red[tid] = lmax; __syncthreads();
    #pragma unroll
    for (int s = 128; s > 0; s >>= 1) {
        if (tid < s) red[tid] = fmaxf(red[tid], red[tid + s]);
        __syncthreads();
    }
    const float m = red[0];
    __syncthreads();

    float lsum = 0.f;
    for (int i = tid; i < n; i += 256) {
        float e = __expf(p[i] - m);
        p[i] = e;
        lsum += e;
    }
    red[tid] = lsum; __syncthreads();
    #pragma unroll
    for (int s = 128; s > 0; s >>= 1) {
        if (tid < s) red[tid] += red[tid + s];
        __syncthreads();
    }
    const float inv = 1.0f / red[0];
    for (int i = tid; i < n; i += 256) p[i] *= inv;
}

// ---------------------------------------------------------------------------
// Launch: pack weights -> fused QKV GEMM (grid.z=3) -> batched NT GEMM ->
// softmax -> batched NN GEMM. All capturable; no allocations.
// ---------------------------------------------------------------------------
extern "C" void kernel_launch(void* const* d_in, const int* in_sizes, int n_in,
                              void* d_out, int out_size)
{
    const float* X  = (const float*)d_in[0];   // [B,S,D] = [8192,1024] flat
    const float* Wq = (const float*)d_in[1];   // [D,U]
    const float* Wk = (const float*)d_in[2];
    const float* Wv = (const float*)d_in[3];
    float* out = (float*)d_out;                // [B,S,U]

    float *qkvp, *wp, *sp;
    cudaGetSymbolAddress((void**)&qkvp, g_qkv);
    cudaGetSymbolAddress((void**)&wp,   g_w);
    cudaGetSymbolAddress((void**)&sp,   g_s);

    const long long sW   = (long long)DD * UU;    // per-z weight stride
    const long long sQKV = (long long)SSQ * UU;   // per-batch Q/K/V stride
    const long long sSC  = (long long)SSQ * SSQ;  // per-batch scores stride
    const size_t    BSU  = (size_t)BB * SSQ * UU; // per-matrix qkv stride

    // Pack the three weight matrices contiguously (capturable D2D copies).
    cudaMemcpyAsync(wp,          Wq, sW * sizeof(float), cudaMemcpyDeviceToDevice, 0);
    cudaMemcpyAsync(wp + sW,     Wk, sW * sizeof(float), cudaMemcpyDeviceToDevice, 0);
    cudaMemcpyAsync(wp + 2 * sW, Wv, sW * sizeof(float), cudaMemcpyDeviceToDevice, 0);

    const dim3 blk(256);

    // 1) Fused projections: z in {Q,K,V}; [8192,1024] @ [1024,1024].
    {
        dim3 grid(UU / 128, (BB * SSQ) / 128, 3);
        gemm128x128<false><<<grid, blk>>>(X, wp, qkvp, BB * SSQ, UU, DD,
                                          0, sW, (long long)BSU);
    }

    float* q = qkvp;
    float* k = qkvp + BSU;
    float* v = qkvp + 2 * BSU;

    // 2) scores[b] = Q[b] @ K[b]^T : [2048,2048], K-dim = 1024.
    {
        dim3 grid(SSQ / 128, SSQ / 128, BB);
        gemm128x128<true><<<grid, blk>>>(q, k, sp, SSQ, SSQ, UU,
                                         sQKV, sQKV, sSC);
    }

    // 3) Row softmax over all B*S rows of length S.
    softmax_rows<<<BB * SSQ, 256>>>(sp, SSQ);

    // 4) out[b] = P[b] @ V[b] : [2048,1024], K-dim = 2048.
    {
        dim3 grid(UU / 128, SSQ / 128, BB);
        gemm128x128<false><<<grid, blk>>>(sp, v, out, SSQ, UU, SSQ,
                                          sSC, sQKV, sQKV);
    }
}

// round 10
// speedup vs baseline: 2.1021x; 2.1021x over previous
#include <cuda_runtime.h>
#include <cuda_bf16.h>
#include <cstdint>

// Problem constants: B=4, S=2048, D=1024, U=1024, fp32 in/out.
#define BB 4
#define SSQ 2048
#define DD 1024
#define UU 1024

// ---------------------------------------------------------------------------
// Global scratch (device globals, allocation-free per harness rules).
// "ext" matrices are K-extended bf16 hi/lo splits:
//   A-side: [hi | lo | hi] along K; B-side: [hi | hi | lo] along K,
// so one plain bf16 NT GEMM over 3K computes Ahi*Bhi + Alo*Bhi + Ahi*Blo
// (the dropped lo*lo term is ~2^-18 relative).
// ---------------------------------------------------------------------------
__device__ __align__(16) __nv_bfloat16 g_xe[(size_t)8192 * 3072];        // X ext
__device__ __align__(16) __nv_bfloat16 g_we[(size_t)3 * 1024 * 3072];    // W^T ext x3
__device__ __align__(16) float         g_qkv[(size_t)3 * BB * SSQ * UU]; // Q,K,V fp32
__device__ __align__(16) __nv_bfloat16 g_qe[(size_t)BB * 2048 * 3072];   // Q ext
__device__ __align__(16) __nv_bfloat16 g_ke[(size_t)BB * 2048 * 3072];   // K ext
__device__ __align__(16) float         g_s[(size_t)BB * SSQ * SSQ];      // scores/P
__device__ __align__(16) __nv_bfloat16 g_pe[(size_t)BB * 2048 * 6144];   // P ext
__device__ __align__(16) __nv_bfloat16 g_ve[(size_t)BB * 1024 * 6144];   // V^T ext

// ---------------------------------------------------------------------------
// Baseline-ISA helpers (sm_80+: cp.async, ldmatrix, mma.sync — all compile
// for plain sm_103; no 'a'-gated features anywhere in this file).
// ---------------------------------------------------------------------------
__device__ __forceinline__ uint32_t smem_u32(const void* p) {
    return (uint32_t)__cvta_generic_to_shared(p);
}
__device__ __forceinline__ void cp16(uint32_t s, const void* g) {
    asm volatile("cp.async.cg.shared.global [%0], [%1], 16;"
                 :: "r"(s), "l"(__cvta_generic_to_global(g)) : "memory");
}
#define CP_COMMIT() asm volatile("cp.async.commit_group;" ::: "memory")
#define CP_WAIT1()  asm volatile("cp.async.wait_group 1;" ::: "memory")
#define CP_WAIT0()  asm volatile("cp.async.wait_group 0;" ::: "memory")

__device__ __forceinline__ void ldsm4(uint32_t* r, uint32_t addr) {
    asm volatile("ldmatrix.sync.aligned.m8n8.x4.shared.b16 {%0,%1,%2,%3}, [%4];"
                 : "=r"(r[0]), "=r"(r[1]), "=r"(r[2]), "=r"(r[3]) : "r"(addr));
}
__device__ __forceinline__ void mma16816(float* c, const uint32_t* a,
                                         const uint32_t* b) {
    asm volatile(
        "mma.sync.aligned.m16n8k16.row.col.f32.bf16.bf16.f32 "
        "{%0,%1,%2,%3}, {%4,%5,%6,%7}, {%8,%9}, {%0,%1,%2,%3};"
        : "+f"(c[0]), "+f"(c[1]), "+f"(c[2]), "+f"(c[3])
        : "r"(a[0]), "r"(a[1]), "r"(a[2]), "r"(a[3]), "r"(b[0]), "r"(b[1]));
}

// ---------------------------------------------------------------------------
// bf16 NT GEMM: C[M,N] fp32 = A[M,Ke] @ B[N,Ke]^T, both bf16 K-major.
// 128x128x32 tile, 256 threads = 8 warps (2m x 4n), warp tile 64x32 as a
// 4x4 grid of m16n8k16 HMMA fragments. cp.async double-buffered smem with
// 80B-padded rows (conflict-free ldmatrix: each 8-lane matrix group hits 8
// distinct 16B segments). Requires M,N % 128 == 0, Ke % 32 == 0.
// blockIdx.z batches via the given strides.
// ---------------------------------------------------------------------------
#define ASTR 40                      // bf16 halves per smem row (80B, padded)
#define TILEH (128 * ASTR)           // halves per tile buffer (10240B)

__global__ __launch_bounds__(256, 2)
void gemm_mma_nt(const __nv_bfloat16* __restrict__ Ag,
                 const __nv_bfloat16* __restrict__ Bg,
                 float* __restrict__ Cg,
                 int N, long long Ke,
                 long long sA, long long sB, long long sC)
{
    __shared__ __align__(16) __nv_bfloat16 smA[2][TILEH];
    __shared__ __align__(16) __nv_bfloat16 smB[2][TILEH];

    const int tid  = threadIdx.x;
    const int lane = tid & 31;
    const int wid  = tid >> 5;
    const int m0w  = (wid >> 2) * 64;   // warp m origin (2 warps)
    const int n0w  = (wid & 3) * 32;    // warp n origin (4 warps)

    const __nv_bfloat16* A =
        Ag + (long long)blockIdx.z * sA + (size_t)blockIdx.y * 128 * Ke;
    const __nv_bfloat16* B =
        Bg + (long long)blockIdx.z * sB + (size_t)blockIdx.x * 128 * Ke;
    float* C = Cg + (long long)blockIdx.z * sC;

    const uint32_t sa[2] = { smem_u32(&smA[0][0]), smem_u32(&smA[1][0]) };
    const uint32_t sb[2] = { smem_u32(&smB[0][0]), smem_u32(&smB[1][0]) };

    // Stage one 128x32-bf16 tile pair (A and B) for chunk ck into buffer b.
    // Each chunk row = 64B of data in 4x16B segments at 80B smem stride.
    auto stage = [&](int ck, int b) {
        const size_t kof = (size_t)ck * 32;
        #pragma unroll
        for (int i = 0; i < 2; ++i) {
            const int id  = tid + i * 256;       // 0..511
            const int row = id >> 2;             // 0..127
            const int seg = id & 3;              // 16B segment
            const uint32_t so = row * 80 + seg * 16;
            const size_t   go = (size_t)row * Ke + kof + seg * 8;
            cp16(sa[b] + so, A + go);
            cp16(sb[b] + so, B + go);
        }
        CP_COMMIT();
    };

    float acc[4][4][4];
    #pragma unroll
    for (int i = 0; i < 4; ++i)
        #pragma unroll
        for (int j = 0; j < 4; ++j)
            #pragma unroll
            for (int k = 0; k < 4; ++k) acc[i][j][k] = 0.f;

    const int nch = (int)(Ke / 32);
    stage(0, 0);
    if (nch > 1) stage(1, 1);

    // ldmatrix lane address components.
    const int arow   = lane & 15;                        // A: rows m..m+15
    const int akh    = (lane >> 4) * 8;                  // A: k halves 0/8
    const int brow   = (lane & 7) + ((lane >> 4) << 3);  // B: n rows, 2 octets
    const int bkh    = ((lane >> 3) & 1) * 8;            // B: k halves 0/8

    for (int t = 0; t < nch; ++t) {
        const int b = t & 1;
        if (t + 1 < nch) CP_WAIT1(); else CP_WAIT0();
        __syncthreads();

        #pragma unroll
        for (int ks = 0; ks < 2; ++ks) {                 // two k16 steps
            uint32_t bfr[2][4];
            #pragma unroll
            for (int h = 0; h < 2; ++h) {                // n octet pairs
                const uint32_t addr = sb[b] +
                    (uint32_t)(((n0w + h * 16 + brow) * ASTR + ks * 16 + bkh) * 2);
                ldsm4(bfr[h], addr);
            }
            #pragma unroll
            for (int mf = 0; mf < 4; ++mf) {
                uint32_t afr[4];
                const uint32_t addr = sa[b] +
                    (uint32_t)(((m0w + mf * 16 + arow) * ASTR + ks * 16 + akh) * 2);
                ldsm4(afr, addr);
                mma16816(acc[mf][0], afr, &bfr[0][0]);
                mma16816(acc[mf][1], afr, &bfr[0][2]);
                mma16816(acc[mf][2], afr, &bfr[1][0]);
                mma16816(acc[mf][3], afr, &bfr[1][2]);
            }
        }
        __syncthreads();
        if (t + 2 < nch) stage(t + 2, b);
    }

    // Epilogue: fragment (mf,nf), thread holds rows (l>>2, l>>2+8),
    // cols nf*8 + (l&3)*2 .. +1.
    const int rr = lane >> 2;
    const int cc = (lane & 3) * 2;
    #pragma unroll
    for (int mf = 0; mf < 4; ++mf) {
        const int gr = blockIdx.y * 128 + m0w + mf * 16 + rr;
        #pragma unroll
        for (int nf = 0; nf < 4; ++nf) {
            const int gc = blockIdx.x * 128 + n0w + nf * 8 + cc;
            float* p = C + (size_t)gr * N + gc;
            *(float2*)p = make_float2(acc[mf][nf][0], acc[mf][nf][1]);
            *(float2*)(p + (size_t)8 * N) =
                make_float2(acc[mf][nf][2], acc[mf][nf][3]);
        }
    }
}

// ---------------------------------------------------------------------------
// split_cols: src fp32 [R,Cc] -> dst bf16 [R, 3*Cc]; block `lo_blk` gets the
// lo residual, the other two get hi. A-side lo_blk=1 -> [hi,lo,hi];
// B-side lo_blk=2 -> [hi,hi,lo].
// ---------------------------------------------------------------------------
__global__ void split_cols(const float* __restrict__ src,
                           __nv_bfloat16* __restrict__ dst,
                           long long Cc, int lo_blk, long long nvec)
{
    union B4 { __nv_bfloat16 b[4]; uint2 u; };
    for (long long i = blockIdx.x * (long long)blockDim.x + threadIdx.x;
         i < nvec; i += (long long)gridDim.x * blockDim.x) {
        const long long e = i * 4;
        const long long r = e / Cc;
        const long long c = e - r * Cc;
        const float4 x = *(const float4*)(src + e);
        B4 h, l;
        h.b[0] = __float2bfloat16_rn(x.x);
        l.b[0] = __float2bfloat16_rn(x.x - __bfloat162float(h.b[0]));
        h.b[1] = __float2bfloat16_rn(x.y);
        l.b[1] = __float2bfloat16_rn(x.y - __bfloat162float(h.b[1]));
        h.b[2] = __float2bfloat16_rn(x.z);
        l.b[2] = __float2bfloat16_rn(x.z - __bfloat162float(h.b[2]));
        h.b[3] = __float2bfloat16_rn(x.w);
        l.b[3] = __float2bfloat16_rn(x.w - __bfloat162float(h.b[3]));
        __nv_bfloat16* dr = dst + r * 3 * Cc + c;
        *(uint2*)(dr)          = (lo_blk == 0) ? l.u : h.u;
        *(uint2*)(dr + Cc)     = (lo_blk == 1) ? l.u : h.u;
        *(uint2*)(dr + 2 * Cc) = (lo_blk == 2) ? l.u : h.u;
    }
}

// ---------------------------------------------------------------------------
// split_transpose: src fp32 [R,Cc] -> dst bf16 [Cc, 3*R] (transposed + split).
// 32x32 tiles via smem. blockDim (32,8); grid (Cc/32, R/32, batches).
// ---------------------------------------------------------------------------
__global__ void split_transpose(const float* __restrict__ src,
                                __nv_bfloat16* __restrict__ dst,
                                int R, int Cc, long long sSrc, long long sDst,
                                int lo_blk)
{
    __shared__ float tile[32][33];
    src += (long long)blockIdx.z * sSrc;
    dst += (long long)blockIdx.z * sDst;
    const int r0 = blockIdx.y * 32, c0 = blockIdx.x * 32;
    const int tx = threadIdx.x, ty = threadIdx.y;

    #pragma unroll
    for (int j = 0; j < 4; ++j) {
        const int r = ty + j * 8;
        tile[r][tx] = src[(size_t)(r0 + r) * Cc + c0 + tx];
    }
    __syncthreads();

    const long long R3 = 3LL * R;
    #pragma unroll
    for (int j = 0; j < 4; ++j) {
        const int c = ty + j * 8;
        const float x = tile[tx][c];
        const __nv_bfloat16 h = __float2bfloat16_rn(x);
        const __nv_bfloat16 l = __float2bfloat16_rn(x - __bfloat162float(h));
        __nv_bfloat16* dr = dst + (size_t)(c0 + c) * R3 + r0 + tx;
        dr[0]             = (lo_blk == 0) ? l : h;
        dr[(size_t)R]     = (lo_blk == 1) ? l : h;
        dr[(size_t)2 * R] = (lo_blk == 2) ? l : h;
    }
}

// ---------------------------------------------------------------------------
// Row softmax in place: one 256-thread block per row of length n (=2048).
// ---------------------------------------------------------------------------
__global__ void softmax_rows(float* __restrict__ S, int n)
{
    __shared__ float red[256];
    float* p = S + (size_t)blockIdx.x * n;
    const int tid = threadIdx.x;

    float lmax = -3.402823466e38f;
    for (int i = tid; i < n; i += 256) lmax = fmaxf(lmax, p[i]);
    red[tid] = lmax; __syncthreads();
    #pragma unroll
    for (int s = 128; s > 0; s >>= 1) {
        if (tid < s) red[tid] = fmaxf(red[tid], red[tid + s]);
        __syncthreads();
    }
    const float m = red[0];
    __syncthreads();

    float lsum = 0.f;
    for (int i = tid; i < n; i += 256) {
        float e = __expf(p[i] - m);
        p[i] = e;
        lsum += e;
    }
    red[tid] = lsum; __syncthreads();
    #pragma unroll
    for (int s = 128; s > 0; s >>= 1) {
        if (tid < s) red[tid] += red[tid + s];
        __syncthreads();
    }
    const float inv = 1.0f / red[0];
    for (int i = tid; i < n; i += 256) p[i] *= inv;
}

// ---------------------------------------------------------------------------
// Launch graph: split(X,W) -> QKV GEMM -> split(Q,K) -> scores GEMM ->
// softmax -> split(P, V^T) -> PV GEMM. All capturable; no allocations.
// ---------------------------------------------------------------------------
extern "C" void kernel_launch(void* const* d_in, const int* in_sizes, int n_in,
                              void* d_out, int out_size)
{
    const float* X  = (const float*)d_in[0];   // [B,S,D] = [8192,1024]
    const float* Wq = (const float*)d_in[1];   // [D,U]
    const float* Wk = (const float*)d_in[2];
    const float* Wv = (const float*)d_in[3];
    float* out = (float*)d_out;                // [B,S,U]

    __nv_bfloat16 *xe, *we, *qe, *ke, *pe, *ve;
    float *qkv, *sp;
    cudaGetSymbolAddress((void**)&xe,  g_xe);
    cudaGetSymbolAddress((void**)&we,  g_we);
    cudaGetSymbolAddress((void**)&qkv, g_qkv);
    cudaGetSymbolAddress((void**)&qe,  g_qe);
    cudaGetSymbolAddress((void**)&ke,  g_ke);
    cudaGetSymbolAddress((void**)&sp,  g_s);
    cudaGetSymbolAddress((void**)&pe,  g_pe);
    cudaGetSymbolAddress((void**)&ve,  g_ve);

    const long long BSU = (long long)BB * SSQ * UU;      // 8388608
    const long long KE1 = 3LL * DD;                      // 3072
    const long long KE2 = 3LL * SSQ;                     // 6144
    const dim3 blk(256);

    // 1) Splits for X (A-side) and W^T (B-side, transposed).
    split_cols<<<2048, 256>>>(X, xe, DD, 1, (long long)8192 * DD / 4);
    {
        dim3 g(UU / 32, DD / 32, 1), b(32, 8);
        split_transpose<<<g, b>>>(Wq, we,                        DD, UU, 0, 0, 2);
        split_transpose<<<g, b>>>(Wk, we + (size_t)UU * KE1,     DD, UU, 0, 0, 2);
        split_transpose<<<g, b>>>(Wv, we + (size_t)2 * UU * KE1, DD, UU, 0, 0, 2);
    }

    // 2) Fused QKV: [8192,3072] @ [1024,3072]^T per z in {Q,K,V}.
    gemm_mma_nt<<<dim3(UU / 128, 8192 / 128, 3), blk>>>(
        xe, we, qkv, UU, KE1, 0, (long long)UU * KE1, (long long)8192 * UU);

    // 3) Splits for Q (A-side) and K (B-side; K is already [S,U] NT layout).
    split_cols<<<2048, 256>>>(qkv,       qe, UU, 1, BSU / 4);
    split_cols<<<2048, 256>>>(qkv + BSU, ke, UU, 2, BSU / 4);

    // 4) scores[b] = Qe[b] @ Ke[b]^T : [2048,2048], Ke-dim 3072.
    gemm_mma_nt<<<dim3(SSQ / 128, SSQ / 128, BB), blk>>>(
        qe, ke, sp, SSQ, KE1,
        (long long)SSQ * KE1, (long long)SSQ * KE1, (long long)SSQ * SSQ);

    // 5) Softmax over all B*S rows.
    softmax_rows<<<BB * SSQ, 256>>>(sp, SSQ);

    // 6) Splits for P (A-side) and V^T (B-side, transposed per batch).
    split_cols<<<2048, 256>>>(sp, pe, SSQ, 1, (long long)8192 * SSQ / 4);
    {
        dim3 g(UU / 32, SSQ / 32, BB), b(32, 8);
        split_transpose<<<g, b>>>(qkv + 2 * BSU, ve, SSQ, UU,
                                  (long long)SSQ * UU, (long long)UU * KE2, 2);
    }

    // 7) out[b] = Pe[b] @ Ve[b]^T : [2048,1024], Ke-dim 6144.
    gemm_mma_nt<<<dim3(UU / 128, SSQ / 128, BB), blk>>>(
        pe, ve, out, UU, KE2,
        (long long)SSQ * KE2, (long long)UU * KE2, (long long)SSQ * UU);
}

// round 13
// speedup vs baseline: 2.1763x; 1.0353x over previous
#include <cuda_runtime.h>
#include <cuda_bf16.h>
#include <cstdint>

// Problem constants: B=4, S=2048, D=1024, U=1024, fp32 in/out.
#define BB 4
#define SSQ 2048
#define DD 1024
#define UU 1024

// ---------------------------------------------------------------------------
// Global scratch (device globals, allocation-free per harness rules).
// K-extended bf16 hi/lo splits: A-side [hi|lo|hi], B-side [hi|hi|lo] along K,
// so one plain bf16 GEMM over 3K computes Ahi*Bhi + Alo*Bhi + Ahi*Blo
// (dropped lo*lo term ~2^-18 relative).
// ---------------------------------------------------------------------------
__device__ __align__(16) __nv_bfloat16 g_xe[(size_t)8192 * 3072];      // X ext (A)
__device__ __align__(16) __nv_bfloat16 g_we[(size_t)3 * 1024 * 3072];  // W^T ext (B) x3
__device__ __align__(16) __nv_bfloat16 g_qe[(size_t)BB * 2048 * 3072]; // Q ext (A)
__device__ __align__(16) __nv_bfloat16 g_ke[(size_t)BB * 2048 * 3072]; // K ext (B, NT)
__device__ __align__(16) __nv_bfloat16 g_ve[(size_t)BB * 6144 * 1024]; // V ext (B, NN rows)
__device__ __align__(16) float         g_s[(size_t)BB * SSQ * SSQ];    // scores
__device__ __align__(16) __nv_bfloat16 g_pe[(size_t)BB * 2048 * 6144]; // P ext (A)

// ---------------------------------------------------------------------------
// Baseline-ISA helpers (sm_80 cp.async / ldmatrix / mma.sync only — nothing
// 'a'-gated; harness compiles for plain sm_103).
// ---------------------------------------------------------------------------
__device__ __forceinline__ uint32_t smem_u32(const void* p) {
    return (uint32_t)__cvta_generic_to_shared(p);
}
__device__ __forceinline__ void cp16(uint32_t s, const void* g) {
    asm volatile("cp.async.cg.shared.global [%0], [%1], 16;"
                 :: "r"(s), "l"(__cvta_generic_to_global(g)) : "memory");
}
#define CP_COMMIT() asm volatile("cp.async.commit_group;" ::: "memory")
#define CP_WAIT1()  asm volatile("cp.async.wait_group 1;" ::: "memory")
#define CP_WAIT0()  asm volatile("cp.async.wait_group 0;" ::: "memory")

__device__ __forceinline__ void ldsm4(uint32_t* r, uint32_t addr) {
    asm volatile("ldmatrix.sync.aligned.m8n8.x4.shared.b16 {%0,%1,%2,%3}, [%4];"
                 : "=r"(r[0]), "=r"(r[1]), "=r"(r[2]), "=r"(r[3]) : "r"(addr));
}
__device__ __forceinline__ void ldsm4t(uint32_t* r, uint32_t addr) {
    asm volatile("ldmatrix.sync.aligned.m8n8.x4.trans.shared.b16 {%0,%1,%2,%3}, [%4];"
                 : "=r"(r[0]), "=r"(r[1]), "=r"(r[2]), "=r"(r[3]) : "r"(addr));
}
__device__ __forceinline__ void mma16816(float* c, const uint32_t* a,
                                         const uint32_t* b) {
    asm volatile(
        "mma.sync.aligned.m16n8k16.row.col.f32.bf16.bf16.f32 "
        "{%0,%1,%2,%3}, {%4,%5,%6,%7}, {%8,%9}, {%0,%1,%2,%3};"
        : "+f"(c[0]), "+f"(c[1]), "+f"(c[2]), "+f"(c[3])
        : "r"(a[0]), "r"(a[1]), "r"(a[2]), "r"(a[3]), "r"(b[0]), "r"(b[1]));
}

// hi/lo bf16 split of an fp32 pair, packed as two b16x2 words.
__device__ __forceinline__ void split2(float f0, float f1,
                                       uint32_t& hip, uint32_t& lop) {
    __nv_bfloat16 h0 = __float2bfloat16_rn(f0);
    __nv_bfloat16 h1 = __float2bfloat16_rn(f1);
    __nv_bfloat16 l0 = __float2bfloat16_rn(f0 - __bfloat162float(h0));
    __nv_bfloat16 l1 = __float2bfloat16_rn(f1 - __bfloat162float(h1));
    hip = (uint32_t)*(uint16_t*)&h0 | ((uint32_t)*(uint16_t*)&h1 << 16);
    lop = (uint32_t)*(uint16_t*)&l0 | ((uint32_t)*(uint16_t*)&l1 << 16);
}

#define ASTR 40                      // A smem row: 32 halves + 8 pad (80B)
#define ATILEH (128 * ASTR)
#define BSTRNN 136                   // NN B smem row: 128 halves + 8 pad (272B)

// ---------------------------------------------------------------------------
// NT GEMM: C[M,N] = A[M,Ke] @ B[N,Ke]^T, bf16 K-major both sides.
// 128x128x32 tile, 8 warps (2m x 4n), warp tile 64x32 of m16n8k16 HMMA,
// cp.async double buffer. QKV=true: epilogue writes ext bf16 per blockIdx.z
// (z=0 qe A-ext cols, z=1 ke B-ext cols, z=2 ve NN-ext rows); else fp32 Cf.
// ---------------------------------------------------------------------------
template <bool QKV>
__global__ __launch_bounds__(256, 2)
void gemm_nt(const __nv_bfloat16* __restrict__ Ag,
             const __nv_bfloat16* __restrict__ Bg,
             float* __restrict__ Cf,
             __nv_bfloat16* __restrict__ dq,
             __nv_bfloat16* __restrict__ dk,
             __nv_bfloat16* __restrict__ dv,
             int N, long long Ke, long long sA, long long sB, long long sC)
{
    __shared__ __align__(16) __nv_bfloat16 smA[2][ATILEH];
    __shared__ __align__(16) __nv_bfloat16 smB[2][ATILEH];

    const int tid  = threadIdx.x;
    const int lane = tid & 31;
    const int wid  = tid >> 5;
    const int m0w  = (wid >> 2) * 64;
    const int n0w  = (wid & 3) * 32;

    const __nv_bfloat16* A =
        Ag + (long long)blockIdx.z * sA + (size_t)blockIdx.y * 128 * Ke;
    const __nv_bfloat16* B =
        Bg + (long long)blockIdx.z * sB + (size_t)blockIdx.x * 128 * Ke;

    const uint32_t sa[2] = { smem_u32(&smA[0][0]), smem_u32(&smA[1][0]) };
    const uint32_t sb[2] = { smem_u32(&smB[0][0]), smem_u32(&smB[1][0]) };

    auto stage = [&](int ck, int b) {
        const size_t kof = (size_t)ck * 32;
        #pragma unroll
        for (int i = 0; i < 2; ++i) {
            const int id  = tid + i * 256;
            const int row = id >> 2;
            const int seg = id & 3;
            const uint32_t so = row * 80 + seg * 16;
            const size_t   go = (size_t)row * Ke + kof + seg * 8;
            cp16(sa[b] + so, A + go);
            cp16(sb[b] + so, B + go);
        }
        CP_COMMIT();
    };

    float acc[4][4][4];
    #pragma unroll
    for (int i = 0; i < 4; ++i)
        #pragma unroll
        for (int j = 0; j < 4; ++j)
            #pragma unroll
            for (int k = 0; k < 4; ++k) acc[i][j][k] = 0.f;

    const int nch = (int)(Ke / 32);
    stage(0, 0);
    if (nch > 1) stage(1, 1);

    const int arow = lane & 15;
    const int akh  = (lane >> 4) * 8;
    const int brow = (lane & 7) + ((lane >> 4) << 3);
    const int bkh  = ((lane >> 3) & 1) * 8;

    for (int t = 0; t < nch; ++t) {
        const int b = t & 1;
        if (t + 1 < nch) CP_WAIT1(); else CP_WAIT0();
        __syncthreads();

        #pragma unroll
        for (int ks = 0; ks < 2; ++ks) {
            uint32_t bfr[2][4];
            #pragma unroll
            for (int h = 0; h < 2; ++h) {
                const uint32_t addr = sb[b] +
                    (uint32_t)(((n0w + h * 16 + brow) * ASTR + ks * 16 + bkh) * 2);
                ldsm4(bfr[h], addr);
            }
            #pragma unroll
            for (int mf = 0; mf < 4; ++mf) {
                uint32_t afr[4];
                const uint32_t addr = sa[b] +
                    (uint32_t)(((m0w + mf * 16 + arow) * ASTR + ks * 16 + akh) * 2);
                ldsm4(afr, addr);
                mma16816(acc[mf][0], afr, &bfr[0][0]);
                mma16816(acc[mf][1], afr, &bfr[0][2]);
                mma16816(acc[mf][2], afr, &bfr[1][0]);
                mma16816(acc[mf][3], afr, &bfr[1][2]);
            }
        }
        __syncthreads();
        if (t + 2 < nch) stage(t + 2, b);
    }

    const int rr  = lane >> 2;
    const int cc2 = (lane & 3) * 2;

    if (!QKV) {
        float* C = Cf + (long long)blockIdx.z * sC;
        #pragma unroll
        for (int mf = 0; mf < 4; ++mf) {
            const int gr = blockIdx.y * 128 + m0w + mf * 16 + rr;
            #pragma unroll
            for (int nf = 0; nf < 4; ++nf) {
                const int gc = blockIdx.x * 128 + n0w + nf * 8 + cc2;
                float* p = C + (size_t)gr * N + gc;
                *(float2*)p = make_float2(acc[mf][nf][0], acc[mf][nf][1]);
                *(float2*)(p + (size_t)8 * N) =
                    make_float2(acc[mf][nf][2], acc[mf][nf][3]);
            }
        }
    } else {
        // N == 1024 here. z=0: qe [M,3072] cols [hi|lo|hi];
        // z=1: ke [M,3072] cols [hi|hi|lo];
        // z=2: ve rows [Vhi;Vhi;Vlo] per batch: [6144,1024].
        const int z = blockIdx.z;
        #pragma unroll
        for (int mf = 0; mf < 4; ++mf) {
            #pragma unroll
            for (int h = 0; h < 2; ++h) {
                const int gr = blockIdx.y * 128 + m0w + mf * 16 + rr + h * 8;
                #pragma unroll
                for (int nf = 0; nf < 4; ++nf) {
                    const int gc = blockIdx.x * 128 + n0w + nf * 8 + cc2;
                    uint32_t hip, lop;
                    split2(acc[mf][nf][2 * h], acc[mf][nf][2 * h + 1], hip, lop);
                    if (z == 0) {
                        __nv_bfloat16* dr = dq + (size_t)gr * 3072 + gc;
                        *(uint32_t*)(dr)        = hip;
                        *(uint32_t*)(dr + 1024) = lop;
                        *(uint32_t*)(dr + 2048) = hip;
                    } else if (z == 1) {
                        __nv_bfloat16* dr = dk + (size_t)gr * 3072 + gc;
                        *(uint32_t*)(dr)        = hip;
                        *(uint32_t*)(dr + 1024) = hip;
                        *(uint32_t*)(dr + 2048) = lop;
                    } else {
                        const size_t base =
                            (size_t)(gr >> 11) * 6144 + (gr & 2047);
                        __nv_bfloat16* dr = dv + base * 1024 + gc;
                        *(uint32_t*)(dr)                      = hip;
                        *(uint32_t*)(dr + (size_t)2048 * 1024) = hip;
                        *(uint32_t*)(dr + (size_t)4096 * 1024) = lop;
                    }
                }
            }
        }
    }
}

// ---------------------------------------------------------------------------
// NN GEMM: C[M,N] = A[M,Ke] @ B[Ke,N], A bf16 K-major, B bf16 N-major rows.
// Same mainloop/warp layout as gemm_nt; B fragments via ldmatrix.trans from a
// 272B-padded [32,128] tile (stride mod 128 = 16 -> conflict-free).
// ---------------------------------------------------------------------------
__global__ __launch_bounds__(256, 2)
void gemm_nn(const __nv_bfloat16* __restrict__ Ag,
             const __nv_bfloat16* __restrict__ Bg,
             float* __restrict__ Cg,
             int N, long long Ke, long long sA, long long sB, long long sC)
{
    __shared__ __align__(16) __nv_bfloat16 smA[2][ATILEH];
    __shared__ __align__(16) __nv_bfloat16 smB[2][32 * BSTRNN];

    const int tid  = threadIdx.x;
    const int lane = tid & 31;
    const int wid  = tid >> 5;
    const int m0w  = (wid >> 2) * 64;
    const int n0w  = (wid & 3) * 32;

    const __nv_bfloat16* A =
        Ag + (long long)blockIdx.z * sA + (size_t)blockIdx.y * 128 * Ke;
    const __nv_bfloat16* B =
        Bg + (long long)blockIdx.z * sB + (size_t)blockIdx.x * 128;
    float* C = Cg + (long long)blockIdx.z * sC;

    const uint32_t sa[2] = { smem_u32(&smA[0][0]), smem_u32(&smA[1][0]) };
    const uint32_t sb[2] = { smem_u32(&smB[0][0]), smem_u32(&smB[1][0]) };

    auto stage = [&](int ck, int b) {
        const size_t kof = (size_t)ck * 32;
        #pragma unroll
        for (int i = 0; i < 2; ++i) {           // A: 128 rows x 4 segs
            const int id  = tid + i * 256;
            const int row = id >> 2;
            const int seg = id & 3;
            cp16(sa[b] + row * 80 + seg * 16,
                 A + (size_t)row * Ke + kof + seg * 8);
        }
        #pragma unroll
        for (int i = 0; i < 2; ++i) {           // B: 32 k-rows x 16 segs
            const int id  = tid + i * 256;
            const int row = id >> 4;
            const int seg = id & 15;
            cp16(sb[b] + row * 272 + seg * 16,
                 B + (size_t)(kof + row) * N + seg * 8);
        }
        CP_COMMIT();
    };

    float acc[4][4][4];
    #pragma unroll
    for (int i = 0; i < 4; ++i)
        #pragma unroll
        for (int j = 0; j < 4; ++j)
            #pragma unroll
            for (int k = 0; k < 4; ++k) acc[i][j][k] = 0.f;

    const int nch = (int)(Ke / 32);
    stage(0, 0);
    if (nch > 1) stage(1, 1);

    const int arow = lane & 15;
    const int akh  = (lane >> 4) * 8;
    // trans-B lane mapping: lanes 0-7 -> (k0:8,n0:8) rows, 8-15 -> (k8:16,n0:8),
    // 16-23 -> (k0:8,n8:16), 24-31 -> (k8:16,n8:16).
    const int bkrow = ((lane >> 3) & 1) * 8 + (lane & 7);
    const int bncol = (lane >> 4) << 3;

    for (int t = 0; t < nch; ++t) {
        const int b = t & 1;
        if (t + 1 < nch) CP_WAIT1(); else CP_WAIT0();
        __syncthreads();

        #pragma unroll
        for (int ks = 0; ks < 2; ++ks) {
            uint32_t bfr[2][4];
            #pragma unroll
            for (int h = 0; h < 2; ++h) {
                const uint32_t addr = sb[b] +
                    (uint32_t)(((ks * 16 + bkrow) * BSTRNN +
                                n0w + h * 16 + bncol) * 2);
                ldsm4t(bfr[h], addr);
            }
            #pragma unroll
            for (int mf = 0; mf < 4; ++mf) {
                uint32_t afr[4];
                const uint32_t addr = sa[b] +
                    (uint32_t)(((m0w + mf * 16 + arow) * ASTR + ks * 16 + akh) * 2);
                ldsm4(afr, addr);
                mma16816(acc[mf][0], afr, &bfr[0][0]);
                mma16816(acc[mf][1], afr, &bfr[0][2]);
                mma16816(acc[mf][2], afr, &bfr[1][0]);
                mma16816(acc[mf][3], afr, &bfr[1][2]);
            }
        }
        __syncthreads();
        if (t + 2 < nch) stage(t + 2, b);
    }

    const int rr  = lane >> 2;
    const int cc2 = (lane & 3) * 2;
    #pragma unroll
    for (int mf = 0; mf < 4; ++mf) {
        const int gr = blockIdx.y * 128 + m0w + mf * 16 + rr;
        #pragma unroll
        for (int nf = 0; nf < 4; ++nf) {
            const int gc = blockIdx.x * 128 + n0w + nf * 8 + cc2;
            float* p = C + (size_t)gr * N + gc;
            *(float2*)p = make_float2(acc[mf][nf][0], acc[mf][nf][1]);
            *(float2*)(p + (size_t)8 * N) =
                make_float2(acc[mf][nf][2], acc[mf][nf][3]);
        }
    }
}

// ---------------------------------------------------------------------------
// split_cols: src fp32 [R,Cc] -> dst bf16 [R,3Cc]; block lo_blk gets lo.
// (Used only for X: lo_blk=1 -> [hi,lo,hi].)
// ---------------------------------------------------------------------------
__global__ void split_cols(const float* __restrict__ src,
                           __nv_bfloat16* __restrict__ dst,
                           long long Cc, int lo_blk, long long nvec)
{
    union B4 { __nv_bfloat16 b[4]; uint2 u; };
    for (long long i = blockIdx.x * (long long)blockDim.x + threadIdx.x;
         i < nvec; i += (long long)gridDim.x * blockDim.x) {
        const long long e = i * 4;
        const long long r = e / Cc;
        const long long c = e - r * Cc;
        const float4 x = *(const float4*)(src + e);
        B4 h, l;
        h.b[0] = __float2bfloat16_rn(x.x);
        l.b[0] = __float2bfloat16_rn(x.x - __bfloat162float(h.b[0]));
        h.b[1] = __float2bfloat16_rn(x.y);
        l.b[1] = __float2bfloat16_rn(x.y - __bfloat162float(h.b[1]));
        h.b[2] = __float2bfloat16_rn(x.z);
        l.b[2] = __float2bfloat16_rn(x.z - __bfloat162float(h.b[2]));
        h.b[3] = __float2bfloat16_rn(x.w);
        l.b[3] = __float2bfloat16_rn(x.w - __bfloat162float(h.b[3]));
        __nv_bfloat16* dr = dst + r * 3 * Cc + c;
        *(uint2*)(dr)          = (lo_blk == 0) ? l.u : h.u;
        *(uint2*)(dr + Cc)     = (lo_blk == 1) ? l.u : h.u;
        *(uint2*)(dr + 2 * Cc) = (lo_blk == 2) ? l.u : h.u;
    }
}

// ---------------------------------------------------------------------------
// split_transpose: src fp32 [R,Cc] -> dst bf16 [Cc,3R]; lo_blk=2 -> [hi,hi,lo].
// (Used only for the three weight matrices.)
// ---------------------------------------------------------------------------
__global__ void split_transpose(const float* __restrict__ src,
                                __nv_bfloat16* __restrict__ dst,
                                int R, int Cc, long long sSrc, long long sDst,
                                int lo_blk)
{
    __shared__ float tile[32][33];
    src += (long long)blockIdx.z * sSrc;
    dst += (long long)blockIdx.z * sDst;
    const int r0 = blockIdx.y * 32, c0 = blockIdx.x * 32;
    const int tx = threadIdx.x, ty = threadIdx.y;

    #pragma unroll
    for (int j = 0; j < 4; ++j) {
        const int r = ty + j * 8;
        tile[r][tx] = src[(size_t)(r0 + r) * Cc + c0 + tx];
    }
    __syncthreads();

    const long long R3 = 3LL * R;
    #pragma unroll
    for (int j = 0; j < 4; ++j) {
        const int c = ty + j * 8;
        const float x = tile[tx][c];
        const __nv_bfloat16 h = __float2bfloat16_rn(x);
        const __nv_bfloat16 l = __float2bfloat16_rn(x - __bfloat162float(h));
        __nv_bfloat16* dr = dst + (size_t)(c0 + c) * R3 + r0 + tx;
        dr[0]             = (lo_blk == 0) ? l : h;
        dr[(size_t)R]     = (lo_blk == 1) ? l : h;
        dr[(size_t)2 * R] = (lo_blk == 2) ? l : h;
    }
}

// ---------------------------------------------------------------------------
// Fused softmax + P-ext: reads one score row (2048 fp32), writes the pe row
// [hi|lo|hi] (6144 bf16). Scores stay read-only. One 256-thread block/row.
// ---------------------------------------------------------------------------
__global__ void softmax_pe(const float* __restrict__ S,
                           __nv_bfloat16* __restrict__ P)
{
    __shared__ float red[256];
    const float* p = S + (size_t)blockIdx.x * SSQ;
    __nv_bfloat16* o = P + (size_t)blockIdx.x * 6144;
    const int tid = threadIdx.x;

    // Each thread owns 4 column pairs: cols 2*tid + j*512 + {0,1}.
    float v[4][2];
    float lmax = -3.402823466e38f;
    #pragma unroll
    for (int j = 0; j < 4; ++j) {
        const float2 x = *(const float2*)(p + 2 * tid + j * 512);
        v[j][0] = x.x; v[j][1] = x.y;
        lmax = fmaxf(lmax, fmaxf(x.x, x.y));
    }
    red[tid] = lmax; __syncthreads();
    #pragma unroll
    for (int s = 128; s > 0; s >>= 1) {
        if (tid < s) red[tid] = fmaxf(red[tid], red[tid + s]);
        __syncthreads();
    }
    const float m = red[0];
    __syncthreads();

    float lsum = 0.f;
    #pragma unroll
    for (int j = 0; j < 4; ++j) {
        v[j][0] = __expf(v[j][0] - m);
        v[j][1] = __expf(v[j][1] - m);
        lsum += v[j][0] + v[j][1];
    }
    red[tid] = lsum; __syncthreads();
    #pragma unroll
    for (int s = 128; s > 0; s >>= 1) {
        if (tid < s) red[tid] += red[tid + s];
        __syncthreads();
    }
    const float inv = 1.0f / red[0];

    #pragma unroll
    for (int j = 0; j < 4; ++j) {
        const int c = 2 * tid + j * 512;
        uint32_t hip, lop;
        split2(v[j][0] * inv, v[j][1] * inv, hip, lop);
        *(uint32_t*)(o + c)        = hip;   // block 0: hi
        *(uint32_t*)(o + 2048 + c) = lop;   // block 1: lo
        *(uint32_t*)(o + 4096 + c) = hip;   // block 2: hi
    }
}

// ---------------------------------------------------------------------------
// Launch graph: split(X), split_transpose(W) -> QKV GEMM (ext epilogues) ->
// scores GEMM -> fused softmax+split -> NN PV GEMM. Capturable; no allocs.
// ---------------------------------------------------------------------------
extern "C" void kernel_launch(void* const* d_in, const int* in_sizes, int n_in,
                              void* d_out, int out_size)
{
    const float* X  = (const float*)d_in[0];   // [B,S,D] = [8192,1024]
    const float* Wq = (const float*)d_in[1];   // [D,U]
    const float* Wk = (const float*)d_in[2];
    const float* Wv = (const float*)d_in[3];
    float* out = (float*)d_out;                // [B,S,U]

    __nv_bfloat16 *xe, *we, *qe, *ke, *ve, *pe;
    float *sp;
    cudaGetSymbolAddress((void**)&xe, g_xe);
    cudaGetSymbolAddress((void**)&we, g_we);
    cudaGetSymbolAddress((void**)&qe, g_qe);
    cudaGetSymbolAddress((void**)&ke, g_ke);
    cudaGetSymbolAddress((void**)&ve, g_ve);
    cudaGetSymbolAddress((void**)&sp, g_s);
    cudaGetSymbolAddress((void**)&pe, g_pe);

    const long long KE1 = 3LL * DD;    // 3072
    const long long KE2 = 3LL * SSQ;   // 6144
    const dim3 blk(256);

    // 1) X ext (A-side) and W^T ext (B-side, transposed).
    split_cols<<<2048, 256>>>(X, xe, DD, 1, (long long)8192 * DD / 4);
    {
        dim3 g(UU / 32, DD / 32, 1), b(32, 8);
        split_transpose<<<g, b>>>(Wq, we,                        DD, UU, 0, 0, 2);
        split_transpose<<<g, b>>>(Wk, we + (size_t)UU * KE1,     DD, UU, 0, 0, 2);
        split_transpose<<<g, b>>>(Wv, we + (size_t)2 * UU * KE1, DD, UU, 0, 0, 2);
    }

    // 2) Fused QKV with ext epilogues: z=0 -> qe, z=1 -> ke, z=2 -> ve.
    gemm_nt<true><<<dim3(UU / 128, 8192 / 128, 3), blk>>>(
        xe, we, nullptr, qe, ke, ve, UU, KE1, 0, (long long)UU * KE1, 0);

    // 3) scores[b] = Qe[b] @ Ke[b]^T : [2048,2048], Ke = 3072.
    gemm_nt<false><<<dim3(SSQ / 128, SSQ / 128, BB), blk>>>(
        qe, ke, sp, nullptr, nullptr, nullptr, SSQ, KE1,
        (long long)SSQ * KE1, (long long)SSQ * KE1, (long long)SSQ * SSQ);

    // 4) Softmax + P ext (A-side) in one pass.
    softmax_pe<<<BB * SSQ, 256>>>(sp, pe);

    // 5) out[b] = Pe[b] @ Ve[b] (NN): [2048,1024], Ke = 6144.
    gemm_nn<<<dim3(UU / 128, SSQ / 128, BB), blk>>>(
        pe, ve, out, UU, KE2,
        (long long)SSQ * KE2, (long long)KE2 * UU, (long long)SSQ * UU);
}

// round 14
// speedup vs baseline: 2.3566x; 1.0828x over previous
#include <cuda_runtime.h>
#include <cuda_bf16.h>
#include <cstdint>

// Problem constants: B=4, S=2048, D=1024, U=1024, fp32 in/out.
#define BB 4
#define SSQ 2048
#define DD 1024
#define UU 1024

// ---------------------------------------------------------------------------
// Global scratch (device globals, allocation-free per harness rules).
// K-extended bf16 hi/lo splits: A-side [hi|lo|hi], B-side [hi|hi|lo] along K,
// so one plain bf16 GEMM over 3K computes Ahi*Bhi + Alo*Bhi + Ahi*Blo
// (dropped lo*lo term ~2^-18 relative).
// ---------------------------------------------------------------------------
__device__ __align__(16) __nv_bfloat16 g_xe[(size_t)8192 * 3072];      // X ext (A)
__device__ __align__(16) __nv_bfloat16 g_we[(size_t)3 * 1024 * 3072];  // W^T ext (B) x3
__device__ __align__(16) __nv_bfloat16 g_qe[(size_t)BB * 2048 * 3072]; // Q ext (A)
__device__ __align__(16) __nv_bfloat16 g_ke[(size_t)BB * 2048 * 3072]; // K ext (B, NT)
__device__ __align__(16) __nv_bfloat16 g_ve[(size_t)BB * 6144 * 1024]; // V ext (B, NN rows)
__device__ __align__(16) float         g_s[(size_t)BB * SSQ * SSQ];    // scores
__device__ __align__(16) __nv_bfloat16 g_pe[(size_t)BB * 2048 * 6144]; // P ext (A)

// ---------------------------------------------------------------------------
// Baseline-ISA helpers (sm_80 cp.async / ldmatrix / mma.sync only — nothing
// 'a'-gated; harness compiles for plain sm_103).
// ---------------------------------------------------------------------------
__device__ __forceinline__ uint32_t smem_u32(const void* p) {
    return (uint32_t)__cvta_generic_to_shared(p);
}
__device__ __forceinline__ void cp16(uint32_t s, const void* g) {
    asm volatile("cp.async.cg.shared.global [%0], [%1], 16;"
                 :: "r"(s), "l"(__cvta_generic_to_global(g)) : "memory");
}
#define CP_COMMIT() asm volatile("cp.async.commit_group;" ::: "memory")
#define CP_WAIT1()  asm volatile("cp.async.wait_group 1;" ::: "memory")
#define CP_WAIT0()  asm volatile("cp.async.wait_group 0;" ::: "memory")

__device__ __forceinline__ void ldsm4(uint32_t* r, uint32_t addr) {
    asm volatile("ldmatrix.sync.aligned.m8n8.x4.shared.b16 {%0,%1,%2,%3}, [%4];"
                 : "=r"(r[0]), "=r"(r[1]), "=r"(r[2]), "=r"(r[3]) : "r"(addr));
}
__device__ __forceinline__ void ldsm4t(uint32_t* r, uint32_t addr) {
    asm volatile("ldmatrix.sync.aligned.m8n8.x4.trans.shared.b16 {%0,%1,%2,%3}, [%4];"
                 : "=r"(r[0]), "=r"(r[1]), "=r"(r[2]), "=r"(r[3]) : "r"(addr));
}
__device__ __forceinline__ void mma16816(float* c, const uint32_t* a,
                                         const uint32_t* b) {
    asm volatile(
        "mma.sync.aligned.m16n8k16.row.col.f32.bf16.bf16.f32 "
        "{%0,%1,%2,%3}, {%4,%5,%6,%7}, {%8,%9}, {%0,%1,%2,%3};"
        : "+f"(c[0]), "+f"(c[1]), "+f"(c[2]), "+f"(c[3])
        : "r"(a[0]), "r"(a[1]), "r"(a[2]), "r"(a[3]), "r"(b[0]), "r"(b[1]));
}

// hi/lo bf16 split of an fp32 pair, packed as two b16x2 words.
__device__ __forceinline__ void split2(float f0, float f1,
                                       uint32_t& hip, uint32_t& lop) {
    __nv_bfloat16 h0 = __float2bfloat16_rn(f0);
    __nv_bfloat16 h1 = __float2bfloat16_rn(f1);
    __nv_bfloat16 l0 = __float2bfloat16_rn(f0 - __bfloat162float(h0));
    __nv_bfloat16 l1 = __float2bfloat16_rn(f1 - __bfloat162float(h1));
    hip = (uint32_t)*(uint16_t*)&h0 | ((uint32_t)*(uint16_t*)&h1 << 16);
    lop = (uint32_t)*(uint16_t*)&l0 | ((uint32_t)*(uint16_t*)&l1 << 16);
}

// K-chunk = 64. A/B NT tiles: 128 rows x 64 halves, padded to 72 halves
// (144B stride: odd multiple of 16B -> conflict-free ldmatrix, like 80B).
#define KCH 64
#define ASTR 72
#define ATILEB (128 * ASTR * 2)          // 18432 B per buffer
#define NT_SMEM (4 * ATILEB)             // 2 bufs x (A + B) = 73728 B
// NN B tile: 64 k-rows x 128 halves, padded to 136 (272B stride).
#define BSTRNN 136
#define BTILEB_NN (64 * BSTRNN * 2)      // 17408 B per buffer
#define NN_SMEM (2 * ATILEB + 2 * BTILEB_NN)  // 71680 B

// ---------------------------------------------------------------------------
// NT GEMM: C[M,N] = A[M,Ke] @ B[N,Ke]^T, bf16 K-major both sides.
// 128x128x64 tile, 8 warps (2m x 4n), warp tile 64x32 of m16n8k16 HMMA,
// cp.async double buffer (KCH=64: 64 HMMAs/warp between barriers).
// QKV=true: epilogue writes ext bf16 per blockIdx.z (z=0 qe A-ext cols,
// z=1 ke B-ext cols, z=2 ve NN-ext rows); else fp32 Cf.
// ---------------------------------------------------------------------------
template <bool QKV>
__global__ __launch_bounds__(256, 2)
void gemm_nt(const __nv_bfloat16* __restrict__ Ag,
             const __nv_bfloat16* __restrict__ Bg,
             float* __restrict__ Cf,
             __nv_bfloat16* __restrict__ dq,
             __nv_bfloat16* __restrict__ dk,
             __nv_bfloat16* __restrict__ dv,
             int N, long long Ke, long long sA, long long sB, long long sC)
{
    extern __shared__ __align__(16) char dsm[];
    const uint32_t base = smem_u32(dsm);
    const uint32_t sa[2] = { base,              base + ATILEB };
    const uint32_t sb[2] = { base + 2 * ATILEB, base + 3 * ATILEB };

    const int tid  = threadIdx.x;
    const int lane = tid & 31;
    const int wid  = tid >> 5;
    const int m0w  = (wid >> 2) * 64;
    const int n0w  = (wid & 3) * 32;

    const __nv_bfloat16* A =
        Ag + (long long)blockIdx.z * sA + (size_t)blockIdx.y * 128 * Ke;
    const __nv_bfloat16* B =
        Bg + (long long)blockIdx.z * sB + (size_t)blockIdx.x * 128 * Ke;

    // Stage one 128x64-half tile pair for chunk ck into buffer b.
    // 8 x 16B segments per row; 4 iters x 256 threads cover 1024 (row,seg).
    auto stage = [&](int ck, int b) {
        const size_t kof = (size_t)ck * KCH;
        #pragma unroll
        for (int i = 0; i < 4; ++i) {
            const int id  = tid + i * 256;       // 0..1023
            const int row = id >> 3;             // 0..127
            const int seg = id & 7;              // 16B segment
            const uint32_t so = row * (ASTR * 2) + seg * 16;
            const size_t   go = (size_t)row * Ke + kof + seg * 8;
            cp16(sa[b] + so, A + go);
            cp16(sb[b] + so, B + go);
        }
        CP_COMMIT();
    };

    float acc[4][4][4];
    #pragma unroll
    for (int i = 0; i < 4; ++i)
        #pragma unroll
        for (int j = 0; j < 4; ++j)
            #pragma unroll
            for (int k = 0; k < 4; ++k) acc[i][j][k] = 0.f;

    const int nch = (int)(Ke / KCH);
    stage(0, 0);
    if (nch > 1) stage(1, 1);

    const int arow = lane & 15;
    const int akh  = (lane >> 4) * 8;
    const int brow = (lane & 7) + ((lane >> 4) << 3);
    const int bkh  = ((lane >> 3) & 1) * 8;

    for (int t = 0; t < nch; ++t) {
        const int b = t & 1;
        if (t + 1 < nch) CP_WAIT1(); else CP_WAIT0();
        __syncthreads();

        #pragma unroll
        for (int ks = 0; ks < 4; ++ks) {                 // four k16 steps
            uint32_t bfr[2][4];
            #pragma unroll
            for (int h = 0; h < 2; ++h) {
                const uint32_t addr = sb[b] +
                    (uint32_t)(((n0w + h * 16 + brow) * ASTR + ks * 16 + bkh) * 2);
                ldsm4(bfr[h], addr);
            }
            #pragma unroll
            for (int mf = 0; mf < 4; ++mf) {
                uint32_t afr[4];
                const uint32_t addr = sa[b] +
                    (uint32_t)(((m0w + mf * 16 + arow) * ASTR + ks * 16 + akh) * 2);
                ldsm4(afr, addr);
                mma16816(acc[mf][0], afr, &bfr[0][0]);
                mma16816(acc[mf][1], afr, &bfr[0][2]);
                mma16816(acc[mf][2], afr, &bfr[1][0]);
                mma16816(acc[mf][3], afr, &bfr[1][2]);
            }
        }
        __syncthreads();
        if (t + 2 < nch) stage(t + 2, b);
    }

    const int rr  = lane >> 2;
    const int cc2 = (lane & 3) * 2;

    if (!QKV) {
        float* C = Cf + (long long)blockIdx.z * sC;
        #pragma unroll
        for (int mf = 0; mf < 4; ++mf) {
            const int gr = blockIdx.y * 128 + m0w + mf * 16 + rr;
            #pragma unroll
            for (int nf = 0; nf < 4; ++nf) {
                const int gc = blockIdx.x * 128 + n0w + nf * 8 + cc2;
                float* p = C + (size_t)gr * N + gc;
                *(float2*)p = make_float2(acc[mf][nf][0], acc[mf][nf][1]);
                *(float2*)(p + (size_t)8 * N) =
                    make_float2(acc[mf][nf][2], acc[mf][nf][3]);
            }
        }
    } else {
        // N == 1024 here. z=0: qe [M,3072] cols [hi|lo|hi];
        // z=1: ke [M,3072] cols [hi|hi|lo];
        // z=2: ve rows [Vhi;Vhi;Vlo] per batch: [6144,1024].
        const int z = blockIdx.z;
        #pragma unroll
        for (int mf = 0; mf < 4; ++mf) {
            #pragma unroll
            for (int h = 0; h < 2; ++h) {
                const int gr = blockIdx.y * 128 + m0w + mf * 16 + rr + h * 8;
                #pragma unroll
                for (int nf = 0; nf < 4; ++nf) {
                    const int gc = blockIdx.x * 128 + n0w + nf * 8 + cc2;
                    uint32_t hip, lop;
                    split2(acc[mf][nf][2 * h], acc[mf][nf][2 * h + 1], hip, lop);
                    if (z == 0) {
                        __nv_bfloat16* dr = dq + (size_t)gr * 3072 + gc;
                        *(uint32_t*)(dr)        = hip;
                        *(uint32_t*)(dr + 1024) = lop;
                        *(uint32_t*)(dr + 2048) = hip;
                    } else if (z == 1) {
                        __nv_bfloat16* dr = dk + (size_t)gr * 3072 + gc;
                        *(uint32_t*)(dr)        = hip;
                        *(uint32_t*)(dr + 1024) = hip;
                        *(uint32_t*)(dr + 2048) = lop;
                    } else {
                        const size_t base2 =
                            (size_t)(gr >> 11) * 6144 + (gr & 2047);
                        __nv_bfloat16* dr = dv + base2 * 1024 + gc;
                        *(uint32_t*)(dr)                       = hip;
                        *(uint32_t*)(dr + (size_t)2048 * 1024) = hip;
                        *(uint32_t*)(dr + (size_t)4096 * 1024) = lop;
                    }
                }
            }
        }
    }
}

// ---------------------------------------------------------------------------
// NN GEMM: C[M,N] = A[M,Ke] @ B[Ke,N], A bf16 K-major, B bf16 N-major rows.
// Same mainloop/warp layout; B fragments via ldmatrix.trans from a 272B-padded
// [64,128] tile. KCH=64 double buffer.
// ---------------------------------------------------------------------------
__global__ __launch_bounds__(256, 2)
void gemm_nn(const __nv_bfloat16* __restrict__ Ag,
             const __nv_bfloat16* __restrict__ Bg,
             float* __restrict__ Cg,
             int N, long long Ke, long long sA, long long sB, long long sC)
{
    extern __shared__ __align__(16) char dsm[];
    const uint32_t base = smem_u32(dsm);
    const uint32_t sa[2] = { base,              base + ATILEB };
    const uint32_t sb[2] = { base + 2 * ATILEB, base + 2 * ATILEB + BTILEB_NN };

    const int tid  = threadIdx.x;
    const int lane = tid & 31;
    const int wid  = tid >> 5;
    const int m0w  = (wid >> 2) * 64;
    const int n0w  = (wid & 3) * 32;

    const __nv_bfloat16* A =
        Ag + (long long)blockIdx.z * sA + (size_t)blockIdx.y * 128 * Ke;
    const __nv_bfloat16* B =
        Bg + (long long)blockIdx.z * sB + (size_t)blockIdx.x * 128;
    float* C = Cg + (long long)blockIdx.z * sC;

    auto stage = [&](int ck, int b) {
        const size_t kof = (size_t)ck * KCH;
        #pragma unroll
        for (int i = 0; i < 4; ++i) {           // A: 128 rows x 8 segs
            const int id  = tid + i * 256;
            const int row = id >> 3;
            const int seg = id & 7;
            cp16(sa[b] + row * (ASTR * 2) + seg * 16,
                 A + (size_t)row * Ke + kof + seg * 8);
        }
        #pragma unroll
        for (int i = 0; i < 4; ++i) {           // B: 64 k-rows x 16 segs
            const int id  = tid + i * 256;
            const int row = id >> 4;
            const int seg = id & 15;
            cp16(sb[b] + row * (BSTRNN * 2) + seg * 16,
                 B + (size_t)(kof + row) * N + seg * 8);
        }
        CP_COMMIT();
    };

    float acc[4][4][4];
    #pragma unroll
    for (int i = 0; i < 4; ++i)
        #pragma unroll
        for (int j = 0; j < 4; ++j)
            #pragma unroll
            for (int k = 0; k < 4; ++k) acc[i][j][k] = 0.f;

    const int nch = (int)(Ke / KCH);
    stage(0, 0);
    if (nch > 1) stage(1, 1);

    const int arow = lane & 15;
    const int akh  = (lane >> 4) * 8;
    const int bkrow = ((lane >> 3) & 1) * 8 + (lane & 7);
    const int bncol = (lane >> 4) << 3;

    for (int t = 0; t < nch; ++t) {
        const int b = t & 1;
        if (t + 1 < nch) CP_WAIT1(); else CP_WAIT0();
        __syncthreads();

        #pragma unroll
        for (int ks = 0; ks < 4; ++ks) {
            uint32_t bfr[2][4];
            #pragma unroll
            for (int h = 0; h < 2; ++h) {
                const uint32_t addr = sb[b] +
                    (uint32_t)(((ks * 16 + bkrow) * BSTRNN +
                                n0w + h * 16 + bncol) * 2);
                ldsm4t(bfr[h], addr);
            }
            #pragma unroll
            for (int mf = 0; mf < 4; ++mf) {
                uint32_t afr[4];
                const uint32_t addr = sa[b] +
                    (uint32_t)(((m0w + mf * 16 + arow) * ASTR + ks * 16 + akh) * 2);
                ldsm4(afr, addr);
                mma16816(acc[mf][0], afr, &bfr[0][0]);
                mma16816(acc[mf][1], afr, &bfr[0][2]);
                mma16816(acc[mf][2], afr, &bfr[1][0]);
                mma16816(acc[mf][3], afr, &bfr[1][2]);
            }
        }
        __syncthreads();
        if (t + 2 < nch) stage(t + 2, b);
    }

    const int rr  = lane >> 2;
    const int cc2 = (lane & 3) * 2;
    #pragma unroll
    for (int mf = 0; mf < 4; ++mf) {
        const int gr = blockIdx.y * 128 + m0w + mf * 16 + rr;
        #pragma unroll
        for (int nf = 0; nf < 4; ++nf) {
            const int gc = blockIdx.x * 128 + n0w + nf * 8 + cc2;
            float* p = C + (size_t)gr * N + gc;
            *(float2*)p = make_float2(acc[mf][nf][0], acc[mf][nf][1]);
            *(float2*)(p + (size_t)8 * N) =
                make_float2(acc[mf][nf][2], acc[mf][nf][3]);
        }
    }
}

// ---------------------------------------------------------------------------
// split_cols: src fp32 [R,Cc] -> dst bf16 [R,3Cc]; block lo_blk gets lo.
// (Used only for X: lo_blk=1 -> [hi,lo,hi].)
// ---------------------------------------------------------------------------
__global__ void split_cols(const float* __restrict__ src,
                           __nv_bfloat16* __restrict__ dst,
                           long long Cc, int lo_blk, long long nvec)
{
    union B4 { __nv_bfloat16 b[4]; uint2 u; };
    for (long long i = blockIdx.x * (long long)blockDim.x + threadIdx.x;
         i < nvec; i += (long long)gridDim.x * blockDim.x) {
        const long long e = i * 4;
        const long long r = e / Cc;
        const long long c = e - r * Cc;
        const float4 x = *(const float4*)(src + e);
        B4 h, l;
        h.b[0] = __float2bfloat16_rn(x.x);
        l.b[0] = __float2bfloat16_rn(x.x - __bfloat162float(h.b[0]));
        h.b[1] = __float2bfloat16_rn(x.y);
        l.b[1] = __float2bfloat16_rn(x.y - __bfloat162float(h.b[1]));
        h.b[2] = __float2bfloat16_rn(x.z);
        l.b[2] = __float2bfloat16_rn(x.z - __bfloat162float(h.b[2]));
        h.b[3] = __float2bfloat16_rn(x.w);
        l.b[3] = __float2bfloat16_rn(x.w - __bfloat162float(h.b[3]));
        __nv_bfloat16* dr = dst + r * 3 * Cc + c;
        *(uint2*)(dr)          = (lo_blk == 0) ? l.u : h.u;
        *(uint2*)(dr + Cc)     = (lo_blk == 1) ? l.u : h.u;
        *(uint2*)(dr + 2 * Cc) = (lo_blk == 2) ? l.u : h.u;
    }
}

// ---------------------------------------------------------------------------
// split_transpose: src fp32 [R,Cc] -> dst bf16 [Cc,3R]; lo_blk=2 -> [hi,hi,lo].
// (Used only for the three weight matrices.)
// ---------------------------------------------------------------------------
__global__ void split_transpose(const float* __restrict__ src,
                                __nv_bfloat16* __restrict__ dst,
                                int R, int Cc, long long sSrc, long long sDst,
                                int lo_blk)
{
    __shared__ float tile[32][33];
    src += (long long)blockIdx.z * sSrc;
    dst += (long long)blockIdx.z * sDst;
    const int r0 = blockIdx.y * 32, c0 = blockIdx.x * 32;
    const int tx = threadIdx.x, ty = threadIdx.y;

    #pragma unroll
    for (int j = 0; j < 4; ++j) {
        const int r = ty + j * 8;
        tile[r][tx] = src[(size_t)(r0 + r) * Cc + c0 + tx];
    }
    __syncthreads();

    const long long R3 = 3LL * R;
    #pragma unroll
    for (int j = 0; j < 4; ++j) {
        const int c = ty + j * 8;
        const float x = tile[tx][c];
        const __nv_bfloat16 h = __float2bfloat16_rn(x);
        const __nv_bfloat16 l = __float2bfloat16_rn(x - __bfloat162float(h));
        __nv_bfloat16* dr = dst + (size_t)(c0 + c) * R3 + r0 + tx;
        dr[0]             = (lo_blk == 0) ? l : h;
        dr[(size_t)R]     = (lo_blk == 1) ? l : h;
        dr[(size_t)2 * R] = (lo_blk == 2) ? l : h;
    }
}

// ---------------------------------------------------------------------------
// Fused softmax + P-ext: reads one score row (2048 fp32), writes the pe row
// [hi|lo|hi] (6144 bf16). One 256-thread block per row.
// ---------------------------------------------------------------------------
__global__ void softmax_pe(const float* __restrict__ S,
                           __nv_bfloat16* __restrict__ P)
{
    __shared__ float red[256];
    const float* p = S + (size_t)blockIdx.x * SSQ;
    __nv_bfloat16* o = P + (size_t)blockIdx.x * 6144;
    const int tid = threadIdx.x;

    float v[4][2];
    float lmax = -3.402823466e38f;
    #pragma unroll
    for (int j = 0; j < 4; ++j) {
        const float2 x = *(const float2*)(p + 2 * tid + j * 512);
        v[j][0] = x.x; v[j][1] = x.y;
        lmax = fmaxf(lmax, fmaxf(x.x, x.y));
    }
    red[tid] = lmax; __syncthreads();
    #pragma unroll
    for (int s = 128; s > 0; s >>= 1) {
        if (tid < s) red[tid] = fmaxf(red[tid], red[tid + s]);
        __syncthreads();
    }
    const float m = red[0];
    __syncthreads();

    float lsum = 0.f;
    #pragma unroll
    for (int j = 0; j < 4; ++j) {
        v[j][0] = __expf(v[j][0] - m);
        v[j][1] = __expf(v[j][1] - m);
        lsum += v[j][0] + v[j][1];
    }
    red[tid] = lsum; __syncthreads();
    #pragma unroll
    for (int s = 128; s > 0; s >>= 1) {
        if (tid < s) red[tid] += red[tid + s];
        __syncthreads();
    }
    const float inv = 1.0f / red[0];

    #pragma unroll
    for (int j = 0; j < 4; ++j) {
        const int c = 2 * tid + j * 512;
        uint32_t hip, lop;
        split2(v[j][0] * inv, v[j][1] * inv, hip, lop);
        *(uint32_t*)(o + c)        = hip;   // block 0: hi
        *(uint32_t*)(o + 2048 + c) = lop;   // block 1: lo
        *(uint32_t*)(o + 4096 + c) = hip;   // block 2: hi
    }
}

// ---------------------------------------------------------------------------
// Launch graph: split(X), split_transpose(W) -> QKV GEMM (ext epilogues) ->
// scores GEMM -> fused softmax+split -> NN PV GEMM. Capturable; no allocs.
// ---------------------------------------------------------------------------
extern "C" void kernel_launch(void* const* d_in, const int* in_sizes, int n_in,
                              void* d_out, int out_size)
{
    const float* X  = (const float*)d_in[0];   // [B,S,D] = [8192,1024]
    const float* Wq = (const float*)d_in[1];   // [D,U]
    const float* Wk = (const float*)d_in[2];
    const float* Wv = (const float*)d_in[3];
    float* out = (float*)d_out;                // [B,S,U]

    __nv_bfloat16 *xe, *we, *qe, *ke, *ve, *pe;
    float *sp;
    cudaGetSymbolAddress((void**)&xe, g_xe);
    cudaGetSymbolAddress((void**)&we, g_we);
    cudaGetSymbolAddress((void**)&qe, g_qe);
    cudaGetSymbolAddress((void**)&ke, g_ke);
    cudaGetSymbolAddress((void**)&ve, g_ve);
    cudaGetSymbolAddress((void**)&sp, g_s);
    cudaGetSymbolAddress((void**)&pe, g_pe);

    // Opt in to >48KB dynamic smem (host-side attribute set; capture-safe).
    static bool attr_done = false;
    if (!attr_done) {
        cudaFuncSetAttribute(gemm_nt<true>,
            cudaFuncAttributeMaxDynamicSharedMemorySize, NT_SMEM);
        cudaFuncSetAttribute(gemm_nt<false>,
            cudaFuncAttributeMaxDynamicSharedMemorySize, NT_SMEM);
        cudaFuncSetAttribute(gemm_nn,
            cudaFuncAttributeMaxDynamicSharedMemorySize, NN_SMEM);
        attr_done = true;
    }

    const long long KE1 = 3LL * DD;    // 3072
    const long long KE2 = 3LL * SSQ;   // 6144
    const dim3 blk(256);

    // 1) X ext (A-side) and W^T ext (B-side, transposed).
    split_cols<<<2048, 256>>>(X, xe, DD, 1, (long long)8192 * DD / 4);
    {
        dim3 g(UU / 32, DD / 32, 1), b(32, 8);
        split_transpose<<<g, b>>>(Wq, we,                        DD, UU, 0, 0, 2);
        split_transpose<<<g, b>>>(Wk, we + (size_t)UU * KE1,     DD, UU, 0, 0, 2);
        split_transpose<<<g, b>>>(Wv, we + (size_t)2 * UU * KE1, DD, UU, 0, 0, 2);
    }

    // 2) Fused QKV with ext epilogues: z=0 -> qe, z=1 -> ke, z=2 -> ve.
    gemm_nt<true><<<dim3(UU / 128, 8192 / 128, 3), blk, NT_SMEM>>>(
        xe, we, nullptr, qe, ke, ve, UU, KE1, 0, (long long)UU * KE1, 0);

    // 3) scores[b] = Qe[b] @ Ke[b]^T : [2048,2048], Ke = 3072.
    gemm_nt<false><<<dim3(SSQ / 128, SSQ / 128, BB), blk, NT_SMEM>>>(
        qe, ke, sp, nullptr, nullptr, nullptr, SSQ, KE1,
        (long long)SSQ * KE1, (long long)SSQ * KE1, (long long)SSQ * SSQ);

    // 4) Softmax + P ext (A-side) in one pass.
    softmax_pe<<<BB * SSQ, 256>>>(sp, pe);

    // 5) out[b] = Pe[b] @ Ve[b] (NN): [2048,1024], Ke = 6144.
    gemm_nn<<<dim3(UU / 128, SSQ / 128, BB), blk, NN_SMEM>>>(
        pe, ve, out, UU, KE2,
        (long long)SSQ * KE2, (long long)KE2 * UU, (long long)SSQ * UU);
}